// round 1
// baseline (speedup 1.0000x reference)
#include <cuda_runtime.h>
#include <cuda_bf16.h>

// Problem constants: B=2, N=2048, D=1024, H=16, hd=64
#define SEQ   2048
#define DIM   1024
#define HEADS 16
#define HD    64
#define BATCH 2
#define MROWS (BATCH * SEQ)   // 4096

// ---------------- scratch (device globals; no allocation allowed) ----------
__device__ float g_q [BATCH * HEADS * SEQ * HD];   // [b,h,n,hd]
__device__ float g_k [BATCH * HEADS * SEQ * HD];
__device__ float g_v [BATCH * HEADS * SEQ * HD];
__device__ float g_ao[MROWS * DIM];                // [b*n, d]

// ---------------- SGEMM: C = A @ W^T + bias, NT form ----------------------
// A: [M,K] row-major, W: [N,K] row-major. 128x128x8 tiles, 256 threads,
// 8x8 micro-tile per thread, float4 everywhere.
// mode 0: write C[m*N+n] = (acc+bias)*scale   (plain row-major)
// mode 1: write to QKV layout [b,h,tok,hd]:   n -> (h,c), m -> (b,tok)
__global__ __launch_bounds__(256) void sgemm_nt(
    const float* __restrict__ A, const float* __restrict__ W,
    const float* __restrict__ bias, float* __restrict__ C,
    int M, int N, int K, int mode, float scale)
{
    __shared__ float As[8][128];
    __shared__ float Bs[8][128];

    const int t    = threadIdx.x;
    const int m0   = blockIdx.y * 128;
    const int n0   = blockIdx.x * 128;
    const int lrow = t >> 1;          // 0..127
    const int lcol = (t & 1) * 4;     // 0 or 4
    const int ty   = t >> 4;          // 0..15
    const int tx   = t & 15;          // 0..15

    float acc[8][8];
#pragma unroll
    for (int i = 0; i < 8; i++)
#pragma unroll
        for (int j = 0; j < 8; j++) acc[i][j] = 0.f;

    const float* Aptr = A + (long)(m0 + lrow) * K + lcol;
    const float* Wptr = W + (long)(n0 + lrow) * K + lcol;

    for (int k0 = 0; k0 < K; k0 += 8) {
        float4 a = *(const float4*)(Aptr + k0);
        float4 w = *(const float4*)(Wptr + k0);
        As[lcol + 0][lrow] = a.x; As[lcol + 1][lrow] = a.y;
        As[lcol + 2][lrow] = a.z; As[lcol + 3][lrow] = a.w;
        Bs[lcol + 0][lrow] = w.x; Bs[lcol + 1][lrow] = w.y;
        Bs[lcol + 2][lrow] = w.z; Bs[lcol + 3][lrow] = w.w;
        __syncthreads();

#pragma unroll
        for (int kk = 0; kk < 8; kk++) {
            float4 a0 = *(const float4*)&As[kk][ty * 4];
            float4 a1 = *(const float4*)&As[kk][ty * 4 + 64];
            float4 b0 = *(const float4*)&Bs[kk][tx * 4];
            float4 b1 = *(const float4*)&Bs[kk][tx * 4 + 64];
            float av[8] = {a0.x, a0.y, a0.z, a0.w, a1.x, a1.y, a1.z, a1.w};
            float bv[8] = {b0.x, b0.y, b0.z, b0.w, b1.x, b1.y, b1.z, b1.w};
#pragma unroll
            for (int i = 0; i < 8; i++)
#pragma unroll
                for (int j = 0; j < 8; j++)
                    acc[i][j] += av[i] * bv[j];
        }
        __syncthreads();
    }

#pragma unroll
    for (int i = 0; i < 8; i++) {
        const int m = m0 + ty * 4 + ((i < 4) ? i : (60 + i));
#pragma unroll
        for (int j = 0; j < 8; j++) {
            const int n = n0 + tx * 4 + ((j < 4) ? j : (60 + j));
            const float val = (acc[i][j] + bias[n]) * scale;
            if (mode == 0) {
                C[(long)m * N + n] = val;
            } else {
                const int b = m >> 11, tok = m & 2047;   // SEQ = 2048
                const int h = n >> 6,  c   = n & 63;     // HD  = 64
                C[(((long)(b * HEADS + h)) * SEQ + tok) * HD + c] = val;
            }
        }
    }
}

// ---------------- Flash attention ------------------------------------------
// Grid: (SEQ/64, HEADS, BATCH), 256 threads (16x16, 4x4 micro-tiles).
// Q pre-scaled by 1/sqrt(DIM). Online softmax over 32 key-blocks of 64.
#define QS_STRIDE 68   // pad 64 -> 68: conflict-free & 16B-aligned rows
#define FA_SMEM ((3 * 64 * QS_STRIDE + 64 * 64) * 4)

__global__ __launch_bounds__(256) void flash_attn(
    const float* __restrict__ q, const float* __restrict__ k,
    const float* __restrict__ v, float* __restrict__ ao)
{
    extern __shared__ float sm[];
    float* Qs = sm;                       // [64][68]
    float* Ks = sm + 64 * QS_STRIDE;      // [64][68]
    float* Ps = sm + 2 * 64 * QS_STRIDE;  // [64][68]
    float* Vs = sm + 3 * 64 * QS_STRIDE;  // [64][64]

    const int t  = threadIdx.x;
    const int ty = t >> 4, tx = t & 15;
    const int qb = blockIdx.x, h = blockIdx.y, b = blockIdx.z;

    const long base = (long)(b * HEADS + h) * SEQ * HD;
    const float* qg = q + base + (long)qb * 64 * HD;

    // load Q block (64 x 64)
#pragma unroll
    for (int it = 0; it < 4; it++) {
        int f = t + it * 256;
        int row = f >> 4, c4 = (f & 15) << 2;
        *(float4*)(Qs + row * QS_STRIDE + c4) = *(const float4*)(qg + row * HD + c4);
    }

    float m_i[4], l_i[4], acc[4][4];
#pragma unroll
    for (int i = 0; i < 4; i++) {
        m_i[i] = -1e30f; l_i[i] = 0.f;
#pragma unroll
        for (int j = 0; j < 4; j++) acc[i][j] = 0.f;
    }

    for (int kb = 0; kb < SEQ / 64; kb++) {
        const float* kg = k + base + (long)kb * 64 * HD;
        const float* vg = v + base + (long)kb * 64 * HD;
#pragma unroll
        for (int it = 0; it < 4; it++) {
            int f = t + it * 256;
            int row = f >> 4, c4 = (f & 15) << 2;
            *(float4*)(Ks + row * QS_STRIDE + c4) = *(const float4*)(kg + row * HD + c4);
            *(float4*)(Vs + row * 64 + c4)        = *(const float4*)(vg + row * HD + c4);
        }
        __syncthreads();

        // S = Q K^T  (4x4 per thread)
        float s[4][4];
#pragma unroll
        for (int i = 0; i < 4; i++)
#pragma unroll
            for (int j = 0; j < 4; j++) s[i][j] = 0.f;

#pragma unroll
        for (int d = 0; d < HD; d += 4) {
            float4 qv[4], kv[4];
#pragma unroll
            for (int i = 0; i < 4; i++)
                qv[i] = *(const float4*)(Qs + (ty * 4 + i) * QS_STRIDE + d);
#pragma unroll
            for (int j = 0; j < 4; j++)
                kv[j] = *(const float4*)(Ks + (tx * 4 + j) * QS_STRIDE + d);
#pragma unroll
            for (int i = 0; i < 4; i++)
#pragma unroll
                for (int j = 0; j < 4; j++)
                    s[i][j] += qv[i].x * kv[j].x + qv[i].y * kv[j].y
                             + qv[i].z * kv[j].z + qv[i].w * kv[j].w;
        }

        // online softmax per row (rows replicated across the 16 tx threads)
#pragma unroll
        for (int i = 0; i < 4; i++) {
            float mx = fmaxf(fmaxf(s[i][0], s[i][1]), fmaxf(s[i][2], s[i][3]));
#pragma unroll
            for (int o = 8; o >= 1; o >>= 1)
                mx = fmaxf(mx, __shfl_xor_sync(0xffffffffu, mx, o));
            const float mn = fmaxf(m_i[i], mx);
            const float corr = __expf(m_i[i] - mn);
            float rs = 0.f;
#pragma unroll
            for (int j = 0; j < 4; j++) {
                s[i][j] = __expf(s[i][j] - mn);
                rs += s[i][j];
            }
#pragma unroll
            for (int o = 8; o >= 1; o >>= 1)
                rs += __shfl_xor_sync(0xffffffffu, rs, o);
            l_i[i] = l_i[i] * corr + rs;
            m_i[i] = mn;
#pragma unroll
            for (int j = 0; j < 4; j++) acc[i][j] *= corr;
            float4 pv4 = make_float4(s[i][0], s[i][1], s[i][2], s[i][3]);
            *(float4*)(Ps + (ty * 4 + i) * QS_STRIDE + tx * 4) = pv4;
        }
        __syncthreads();

        // O += P @ V
#pragma unroll
        for (int kk = 0; kk < 64; kk += 4) {
            float4 vv0 = *(const float4*)(Vs + (kk + 0) * 64 + tx * 4);
            float4 vv1 = *(const float4*)(Vs + (kk + 1) * 64 + tx * 4);
            float4 vv2 = *(const float4*)(Vs + (kk + 2) * 64 + tx * 4);
            float4 vv3 = *(const float4*)(Vs + (kk + 3) * 64 + tx * 4);
#pragma unroll
            for (int i = 0; i < 4; i++) {
                float4 pv = *(const float4*)(Ps + (ty * 4 + i) * QS_STRIDE + kk);
                acc[i][0] += pv.x * vv0.x + pv.y * vv1.x + pv.z * vv2.x + pv.w * vv3.x;
                acc[i][1] += pv.x * vv0.y + pv.y * vv1.y + pv.z * vv2.y + pv.w * vv3.y;
                acc[i][2] += pv.x * vv0.z + pv.y * vv1.z + pv.z * vv2.z + pv.w * vv3.z;
                acc[i][3] += pv.x * vv0.w + pv.y * vv1.w + pv.z * vv2.w + pv.w * vv3.w;
            }
        }
        __syncthreads();
    }

    // epilogue: write to [b, tok, d] layout for the output projection
#pragma unroll
    for (int i = 0; i < 4; i++) {
        const float inv = 1.f / l_i[i];
        const int tok = qb * 64 + ty * 4 + i;
        float4 o = make_float4(acc[i][0] * inv, acc[i][1] * inv,
                               acc[i][2] * inv, acc[i][3] * inv);
        *(float4*)(ao + ((long)(b * SEQ + tok)) * DIM + h * HD + tx * 4) = o;
    }
}

// ---------------- launch ----------------------------------------------------
extern "C" void kernel_launch(void* const* d_in, const int* in_sizes, int n_in,
                              void* d_out, int out_size)
{
    const float* x  = (const float*)d_in[0];
    const float* Wq = (const float*)d_in[1];
    const float* bq = (const float*)d_in[2];
    const float* Wk = (const float*)d_in[3];
    const float* bk = (const float*)d_in[4];
    const float* Wv = (const float*)d_in[5];
    const float* bv = (const float*)d_in[6];
    const float* Wo = (const float*)d_in[7];
    const float* bo = (const float*)d_in[8];
    float* out = (float*)d_out;

    float *gq, *gk, *gv, *gao;
    cudaGetSymbolAddress((void**)&gq,  g_q);
    cudaGetSymbolAddress((void**)&gk,  g_k);
    cudaGetSymbolAddress((void**)&gv,  g_v);
    cudaGetSymbolAddress((void**)&gao, g_ao);

    cudaFuncSetAttribute(flash_attn,
                         cudaFuncAttributeMaxDynamicSharedMemorySize, FA_SMEM);

    dim3 gg(DIM / 128, MROWS / 128);   // (8, 32)
    const float qscale = 0.03125f;     // 1/sqrt(1024) exactly

    sgemm_nt<<<gg, 256>>>(x, Wq, bq, gq, MROWS, DIM, DIM, 1, qscale);
    sgemm_nt<<<gg, 256>>>(x, Wk, bk, gk, MROWS, DIM, DIM, 1, 1.f);
    sgemm_nt<<<gg, 256>>>(x, Wv, bv, gv, MROWS, DIM, DIM, 1, 1.f);

    flash_attn<<<dim3(SEQ / 64, HEADS, BATCH), 256, FA_SMEM>>>(gq, gk, gv, gao);

    sgemm_nt<<<gg, 256>>>(gao, Wo, bo, out, MROWS, DIM, DIM, 0, 1.f);
}

// round 2
// speedup vs baseline: 5.8358x; 5.8358x over previous
#include <cuda_runtime.h>

// Problem constants: B=2, N=2048, D=1024, H=16, hd=64
#define SEQ   2048
#define DIM   1024
#define HEADS 16
#define HD    64
#define BATCH 2
#define MROWS (BATCH * SEQ)   // 4096

// ---------------- scratch (device globals; no allocation allowed) ----------
__device__ float g_q [BATCH * HEADS * SEQ * HD];   // [b,h,n,hd]
__device__ float g_k [BATCH * HEADS * SEQ * HD];
__device__ float g_v [BATCH * HEADS * SEQ * HD];
__device__ float g_ao[MROWS * DIM];                // [b*n, d]

// ---------------- tf32 helpers ---------------------------------------------
__device__ __forceinline__ unsigned f2tf(float f) {
    unsigned u;
    asm("cvt.rna.tf32.f32 %0, %1;" : "=r"(u) : "f"(f));
    return u;
}

// mma.m16n8k8 row.col f32 += tf32 * tf32
__device__ __forceinline__ void mma_tf32(float c[4], const unsigned a[4], const unsigned b[2]) {
    asm volatile(
        "mma.sync.aligned.m16n8k8.row.col.f32.tf32.tf32.f32 "
        "{%0,%1,%2,%3}, {%4,%5,%6,%7}, {%8,%9}, {%0,%1,%2,%3};"
        : "+f"(c[0]), "+f"(c[1]), "+f"(c[2]), "+f"(c[3])
        : "r"(a[0]), "r"(a[1]), "r"(a[2]), "r"(a[3]), "r"(b[0]), "r"(b[1]));
}

// ---------------- GEMM: C = (A @ W^T + bias) * scale  (tf32 tensor cores) --
// A: [M=4096, K=1024] row-major; W: [N=1024, K=1024] row-major.
// 128x128 CTA tile, 8 warps = 2x4, warp tile 64x32 (4x4 mma tiles), K-tile 32.
// mode 0: row-major out. mode 1: scatter to QKV layout [b,h,tok,hd].
#define SST 36

__global__ __launch_bounds__(256) void sgemm_tc(
    const float* __restrict__ A, const float* __restrict__ W,
    const float* __restrict__ bias, float* __restrict__ C,
    int mode, float scale)
{
    __shared__ float As[128][SST];
    __shared__ float Ws[128][SST];

    const int t = threadIdx.x;
    const int w = t >> 5, lane = t & 31;
    const int g = lane >> 2, tid = lane & 3;
    const int m0 = blockIdx.y * 128, n0 = blockIdx.x * 128;
    const int wr = (w >> 2) * 64;    // warp row offset (0 or 64)
    const int wc = (w & 3) * 32;     // warp col offset

    float acc[4][4][4];
#pragma unroll
    for (int mi = 0; mi < 4; mi++)
#pragma unroll
        for (int ni = 0; ni < 4; ni++)
#pragma unroll
            for (int e = 0; e < 4; e++) acc[mi][ni][e] = 0.f;

    for (int k0 = 0; k0 < DIM; k0 += 32) {
#pragma unroll
        for (int p = 0; p < 4; p++) {
            int idx = t + p * 256;
            int r = idx >> 3, c = (idx & 7) * 4;
            *(float4*)&As[r][c] = *(const float4*)(A + (long)(m0 + r) * DIM + k0 + c);
            *(float4*)&Ws[r][c] = *(const float4*)(W + (long)(n0 + r) * DIM + k0 + c);
        }
        __syncthreads();

#pragma unroll
        for (int ks = 0; ks < 4; ks++) {
            const int kk = ks * 8;
            unsigned af[4][4], bf[4][2];
#pragma unroll
            for (int mi = 0; mi < 4; mi++) {
                const int rb = wr + mi * 16;
                af[mi][0] = f2tf(As[rb + g    ][kk + tid    ]);
                af[mi][1] = f2tf(As[rb + g + 8][kk + tid    ]);
                af[mi][2] = f2tf(As[rb + g    ][kk + tid + 4]);
                af[mi][3] = f2tf(As[rb + g + 8][kk + tid + 4]);
            }
#pragma unroll
            for (int ni = 0; ni < 4; ni++) {
                const int nb = wc + ni * 8;
                bf[ni][0] = f2tf(Ws[nb + g][kk + tid    ]);
                bf[ni][1] = f2tf(Ws[nb + g][kk + tid + 4]);
            }
#pragma unroll
            for (int mi = 0; mi < 4; mi++)
#pragma unroll
                for (int ni = 0; ni < 4; ni++)
                    mma_tf32(acc[mi][ni], af[mi], bf[ni]);
        }
        __syncthreads();
    }

    // epilogue
#pragma unroll
    for (int mi = 0; mi < 4; mi++) {
        const int r0 = m0 + wr + mi * 16 + g;
#pragma unroll
        for (int ni = 0; ni < 4; ni++) {
            const int c0 = n0 + wc + ni * 8 + tid * 2;
            const float b0 = bias[c0], b1 = bias[c0 + 1];
#pragma unroll
            for (int half = 0; half < 2; half++) {
                const int r = r0 + half * 8;
                const float v0 = (acc[mi][ni][half * 2 + 0] + b0) * scale;
                const float v1 = (acc[mi][ni][half * 2 + 1] + b1) * scale;
                if (mode == 0) {
                    *(float2*)(C + (long)r * DIM + c0) = make_float2(v0, v1);
                } else {
                    const int b   = r >> 11, tok = r & 2047;   // SEQ=2048
                    const int h   = c0 >> 6, cc  = c0 & 63;    // HD=64
                    *(float2*)(C + (((long)(b * HEADS + h)) * SEQ + tok) * HD + cc)
                        = make_float2(v0, v1);
                }
            }
        }
    }
}

// ---------------- Flash attention (tf32 tensor cores) -----------------------
// CTA: 256 threads (8 warps), 128 queries; each warp owns 16 query rows.
// K-block 64. S and P@V via m16n8k8 tf32 mma; online softmax on C fragments.
#define QB  128
#define KB  64
#define PST 68   // Q/K/P smem stride (conflict-free fragment loads)
#define VST 72   // V smem stride
#define FA_SMEM ((QB * PST + KB * PST + QB * PST + KB * VST) * 4)

__global__ __launch_bounds__(256, 2) void flash_tc(
    const float* __restrict__ q, const float* __restrict__ k,
    const float* __restrict__ v, float* __restrict__ ao)
{
    extern __shared__ float sm[];
    float* Qs = sm;                  // [128][68]
    float* Ks = Qs + QB * PST;       // [64][68]
    float* Ps = Ks + KB * PST;       // [128][68]
    float* Vs = Ps + QB * PST;       // [64][72]

    const int t = threadIdx.x;
    const int w = t >> 5, lane = t & 31;
    const int g = lane >> 2, tid = lane & 3;
    const int qb = blockIdx.x, h = blockIdx.y, b = blockIdx.z;
    const int r0 = w * 16;           // warp's query row block

    const long base = (long)(b * HEADS + h) * SEQ * HD;
    const float* qg = q + base + (long)qb * QB * HD;

    // load Q block (128 x 64)
#pragma unroll
    for (int p = 0; p < 8; p++) {
        int idx = t + p * 256;
        int r = idx >> 4, c = (idx & 15) * 4;
        *(float4*)(Qs + r * PST + c) = *(const float4*)(qg + r * HD + c);
    }

    float o[8][4];
#pragma unroll
    for (int ni = 0; ni < 8; ni++)
#pragma unroll
        for (int e = 0; e < 4; e++) o[ni][e] = 0.f;
    float m0r = -1e30f, m1r = -1e30f, l0 = 0.f, l1 = 0.f;

    for (int kb = 0; kb < SEQ / KB; kb++) {
        __syncthreads();
        const float* kg = k + base + (long)kb * KB * HD;
        const float* vg = v + base + (long)kb * KB * HD;
#pragma unroll
        for (int p = 0; p < 4; p++) {
            int idx = t + p * 256;
            int r = idx >> 4, c = (idx & 15) * 4;
            *(float4*)(Ks + r * PST + c) = *(const float4*)(kg + r * HD + c);
            *(float4*)(Vs + r * VST + c) = *(const float4*)(vg + r * HD + c);
        }
        __syncthreads();

        // ---- S = Q K^T : 16x64 per warp ----
        float s[8][4];
#pragma unroll
        for (int ni = 0; ni < 8; ni++)
#pragma unroll
            for (int e = 0; e < 4; e++) s[ni][e] = 0.f;

#pragma unroll
        for (int ks = 0; ks < 8; ks++) {
            const int kk = ks * 8;
            unsigned aq[4];
            aq[0] = f2tf(Qs[(r0 + g    ) * PST + kk + tid    ]);
            aq[1] = f2tf(Qs[(r0 + g + 8) * PST + kk + tid    ]);
            aq[2] = f2tf(Qs[(r0 + g    ) * PST + kk + tid + 4]);
            aq[3] = f2tf(Qs[(r0 + g + 8) * PST + kk + tid + 4]);
#pragma unroll
            for (int ni = 0; ni < 8; ni++) {
                unsigned bk[2];
                bk[0] = f2tf(Ks[(ni * 8 + g) * PST + kk + tid    ]);
                bk[1] = f2tf(Ks[(ni * 8 + g) * PST + kk + tid + 4]);
                mma_tf32(s[ni], aq, bk);
            }
        }

        // ---- online softmax (rows g and g+8 of this warp) ----
        float mx0 = -1e30f, mx1 = -1e30f;
#pragma unroll
        for (int ni = 0; ni < 8; ni++) {
            mx0 = fmaxf(mx0, fmaxf(s[ni][0], s[ni][1]));
            mx1 = fmaxf(mx1, fmaxf(s[ni][2], s[ni][3]));
        }
        mx0 = fmaxf(mx0, __shfl_xor_sync(0xffffffffu, mx0, 1));
        mx0 = fmaxf(mx0, __shfl_xor_sync(0xffffffffu, mx0, 2));
        mx1 = fmaxf(mx1, __shfl_xor_sync(0xffffffffu, mx1, 1));
        mx1 = fmaxf(mx1, __shfl_xor_sync(0xffffffffu, mx1, 2));

        const float mn0 = fmaxf(m0r, mx0), mn1 = fmaxf(m1r, mx1);
        const float cr0 = __expf(m0r - mn0), cr1 = __expf(m1r - mn1);
        float rs0 = 0.f, rs1 = 0.f;
#pragma unroll
        for (int ni = 0; ni < 8; ni++) {
            s[ni][0] = __expf(s[ni][0] - mn0);
            s[ni][1] = __expf(s[ni][1] - mn0);
            s[ni][2] = __expf(s[ni][2] - mn1);
            s[ni][3] = __expf(s[ni][3] - mn1);
            rs0 += s[ni][0] + s[ni][1];
            rs1 += s[ni][2] + s[ni][3];
        }
        rs0 += __shfl_xor_sync(0xffffffffu, rs0, 1);
        rs0 += __shfl_xor_sync(0xffffffffu, rs0, 2);
        rs1 += __shfl_xor_sync(0xffffffffu, rs1, 1);
        rs1 += __shfl_xor_sync(0xffffffffu, rs1, 2);

        l0 = l0 * cr0 + rs0;  l1 = l1 * cr1 + rs1;
        m0r = mn0;            m1r = mn1;

#pragma unroll
        for (int ni = 0; ni < 8; ni++) {
            o[ni][0] *= cr0; o[ni][1] *= cr0;
            o[ni][2] *= cr1; o[ni][3] *= cr1;
            // store P rows (warp-private)
            *(float2*)(Ps + (r0 + g    ) * PST + ni * 8 + tid * 2) = make_float2(s[ni][0], s[ni][1]);
            *(float2*)(Ps + (r0 + g + 8) * PST + ni * 8 + tid * 2) = make_float2(s[ni][2], s[ni][3]);
        }
        __syncwarp();

        // ---- O += P @ V ----
#pragma unroll
        for (int ks = 0; ks < 8; ks++) {
            const int kk = ks * 8;
            unsigned ap[4];
            ap[0] = f2tf(Ps[(r0 + g    ) * PST + kk + tid    ]);
            ap[1] = f2tf(Ps[(r0 + g + 8) * PST + kk + tid    ]);
            ap[2] = f2tf(Ps[(r0 + g    ) * PST + kk + tid + 4]);
            ap[3] = f2tf(Ps[(r0 + g + 8) * PST + kk + tid + 4]);
#pragma unroll
            for (int ni = 0; ni < 8; ni++) {
                unsigned bv[2];
                bv[0] = f2tf(Vs[(kk + tid    ) * VST + ni * 8 + g]);
                bv[1] = f2tf(Vs[(kk + tid + 4) * VST + ni * 8 + g]);
                mma_tf32(o[ni], ap, bv);
            }
        }
    }

    // epilogue -> [b, tok, d] for the output projection
    const float inv0 = 1.f / l0, inv1 = 1.f / l1;
    const int tok0 = qb * QB + r0 + g;
    float* dst0 = ao + ((long)(b * SEQ) + tok0) * DIM + h * HD;
    float* dst1 = dst0 + 8 * DIM;
#pragma unroll
    for (int ni = 0; ni < 8; ni++) {
        const int col = ni * 8 + tid * 2;
        *(float2*)(dst0 + col) = make_float2(o[ni][0] * inv0, o[ni][1] * inv0);
        *(float2*)(dst1 + col) = make_float2(o[ni][2] * inv1, o[ni][3] * inv1);
    }
}

// ---------------- launch ----------------------------------------------------
extern "C" void kernel_launch(void* const* d_in, const int* in_sizes, int n_in,
                              void* d_out, int out_size)
{
    const float* x  = (const float*)d_in[0];
    const float* Wq = (const float*)d_in[1];
    const float* bq = (const float*)d_in[2];
    const float* Wk = (const float*)d_in[3];
    const float* bk = (const float*)d_in[4];
    const float* Wv = (const float*)d_in[5];
    const float* bv = (const float*)d_in[6];
    const float* Wo = (const float*)d_in[7];
    const float* bo = (const float*)d_in[8];
    float* out = (float*)d_out;

    float *gq, *gk, *gv, *gao;
    cudaGetSymbolAddress((void**)&gq,  g_q);
    cudaGetSymbolAddress((void**)&gk,  g_k);
    cudaGetSymbolAddress((void**)&gv,  g_v);
    cudaGetSymbolAddress((void**)&gao, g_ao);

    cudaFuncSetAttribute(flash_tc,
                         cudaFuncAttributeMaxDynamicSharedMemorySize, FA_SMEM);

    dim3 gg(DIM / 128, MROWS / 128);   // (8, 32)
    const float qscale = 0.03125f;     // 1/sqrt(1024)

    sgemm_tc<<<gg, 256>>>(x, Wq, bq, gq, 1, qscale);
    sgemm_tc<<<gg, 256>>>(x, Wk, bk, gk, 1, 1.f);
    sgemm_tc<<<gg, 256>>>(x, Wv, bv, gv, 1, 1.f);

    flash_tc<<<dim3(SEQ / QB, HEADS, BATCH), 256, FA_SMEM>>>(gq, gk, gv, gao);

    sgemm_tc<<<gg, 256>>>(gao, Wo, bo, out, 0, 1.f);
}